// round 9
// baseline (speedup 1.0000x reference)
#include <cuda_runtime.h>

#define T_DIM 2048
#define MAX_B 8192
#define BLOCK 32
#define ROWS_PER_THREAD 2
#define FULLMASK 0xffffffffu

// Single 64-bit accumulator: bits[63:16] = biased fixed-point sum (per-thread
// scale 2^19, bias 2^38 per arriving warp), bits[15:0] = arrived-warp count.
// All additions are integer -> associative -> bitwise-deterministic in any
// arrival order. Last arriver holds the grand total in-hand, stores the mean,
// resets for the next graph replay.
__device__ unsigned long long g_acc = 0ULL;

// Per-row loss given tier-A prefetched registers; falls back to memory for
// the (astronomically rare) tier-B/C cases.
__device__ __forceinline__ float row_loss(const float* __restrict__ p,
                                          const int* __restrict__ lab,
                                          const float pf[24], const int la[16]) {
    const int lab0 = la[0];
    int ind0 = T_DIM;
    #pragma unroll
    for (int k = 15; k >= 1; k--)              // descending: smallest k wins
        if (la[k] != lab0) ind0 = k;

    if (ind0 <= 15) {
        // ---- TIER A (P ~ 1 - 2^-15): prefix + full n=8 window, regs only ----
        float S = 0.f, cp = 1.f;
        float term1 = 0.f, cpw = 1.f, cpl = 1.f, pl = 0.f;
        #pragma unroll
        for (int k = 0; k < 24; k++) {
            const float pk = pf[k];
            if (k < ind0) {                     // false-alarm prefix
                S  += (float)(k + 1) * pk * cp;
                cp *= 1.f - pk;
            }
            if (k >= ind0 && k < ind0 + 8) {    // delay window
                const int kk = k - ind0;
                term1 += (float)(kk + 1) * pk * cpw;
                if (kk == 7) { cpl = cpw; pl = pk; }
                cpw *= 1.f - pk;
            }
        }
        const float fa = 1.f - S;
        const float dd = term1 + 72.f * cpl * (1.f - pl);   // n=8, W+1=9
        return 0.5f * dd + 0.5f * fa;                       // ALPHA=0.5
    }

    // ---- TIER B (P ~ 2^-15): ONE more bulk round trip, no serial chase ----
    int4   m0 = __ldg((const int4*)(lab + 16));
    int4   m1 = __ldg((const int4*)(lab + 20));
    int4   m2 = __ldg((const int4*)(lab + 24));
    int4   m3 = __ldg((const int4*)(lab + 28));
    int4   m4 = __ldg((const int4*)(lab + 32));
    int4   m5 = __ldg((const int4*)(lab + 36));
    int4   m6 = __ldg((const int4*)(lab + 40));
    int4   m7 = __ldg((const int4*)(lab + 44));
    float4 r0 = __ldg((const float4*)(p + 24));
    float4 r1 = __ldg((const float4*)(p + 28));
    float4 r2 = __ldg((const float4*)(p + 32));
    float4 r3 = __ldg((const float4*)(p + 36));
    float4 r4 = __ldg((const float4*)(p + 40));
    float4 r5 = __ldg((const float4*)(p + 44));
    float4 r6 = __ldg((const float4*)(p + 48));
    float4 r7 = __ldg((const float4*)(p + 52));

    const int   lb[32] = {m0.x,m0.y,m0.z,m0.w, m1.x,m1.y,m1.z,m1.w,
                          m2.x,m2.y,m2.z,m2.w, m3.x,m3.y,m3.z,m3.w,
                          m4.x,m4.y,m4.z,m4.w, m5.x,m5.y,m5.z,m5.w,
                          m6.x,m6.y,m6.z,m6.w, m7.x,m7.y,m7.z,m7.w};
    const float pg[32] = {r0.x,r0.y,r0.z,r0.w, r1.x,r1.y,r1.z,r1.w,
                          r2.x,r2.y,r2.z,r2.w, r3.x,r3.y,r3.z,r3.w,
                          r4.x,r4.y,r4.z,r4.w, r5.x,r5.y,r5.z,r5.w,
                          r6.x,r6.y,r6.z,r6.w, r7.x,r7.y,r7.z,r7.w};

    #pragma unroll
    for (int k = 31; k >= 0; k--)
        if (lb[k] != lab0) ind0 = 16 + k;

    if (ind0 <= 47) {
        float S = 0.f, cp = 1.f;
        float term1 = 0.f, cpw = 1.f, cpl = 1.f, pl = 0.f;
        #pragma unroll
        for (int k = 0; k < 56; k++) {
            const float pk = (k < 24) ? pf[k] : pg[k - 24];
            if (k < ind0) {
                S  += (float)(k + 1) * pk * cp;
                cp *= 1.f - pk;
            }
            if (k >= ind0 && k < ind0 + 8) {
                const int kk = k - ind0;
                term1 += (float)(kk + 1) * pk * cpw;
                if (kk == 7) { cpl = cpw; pl = pk; }
                cpw *= 1.f - pk;
            }
        }
        const float fa = 1.f - S;
        const float dd = term1 + 72.f * cpl * (1.f - pl);
        return 0.5f * dd + 0.5f * fa;
    }

    // ---- TIER C (P ~ 2^-47): fully general, correctness only ----
    ind0 = T_DIM;
    for (int base = 48; base < T_DIM; base += 4) {
        int4 v = __ldg((const int4*)(lab + base));
        if (v.x != lab0) { ind0 = base;     break; }
        if (v.y != lab0) { ind0 = base + 1; break; }
        if (v.z != lab0) { ind0 = base + 2; break; }
        if (v.w != lab0) { ind0 = base + 3; break; }
    }
    const bool has_change = (ind0 < T_DIM);
    const int  L = has_change ? ind0 : T_DIM;
    float S = 0.f, cp = 1.f;
    for (int k = 0; k < L; k++) {
        const float pk = p[k];
        S  += (float)(k + 1) * pk * cp;
        cp *= 1.f - pk;
    }
    const float fa = 1.f - S;
    if (has_change) {
        int n = T_DIM - ind0; if (n > 8) n = 8;
        float cpw = 1.f, term1 = 0.f, cpl = 1.f, pl = 0.f;
        for (int kk = 0; kk < n; kk++) {
            const float pk = p[ind0 + kk];
            term1 += (float)(kk + 1) * pk * cpw;
            if (kk == n - 1) { cpl = cpw; pl = pk; }
            cpw *= 1.f - pk;
        }
        const float dd = term1 + (float)n * 9.f * cpl * (1.f - pl);
        return 0.5f * dd + 0.5f * fa;
    }
    return fa;
}

__global__ __launch_bounds__(BLOCK)
void fused_loss_kernel(const float* __restrict__ outputs,
                       const int* __restrict__ labels,
                       float* __restrict__ out, int B) {
    const int row0 = blockIdx.x * (BLOCK * ROWS_PER_THREAD) + threadIdx.x;
    const int row1 = row0 + BLOCK;

    float acc = 0.0f;

    // ---- issue ALL 20 tier-A LDG.128 (both rows) back-to-back: one round trip ----
    const float* p0   = outputs + (size_t)row0 * T_DIM;
    const int*   lab0p = labels + (size_t)row0 * T_DIM;
    const float* p1   = outputs + (size_t)row1 * T_DIM;
    const int*   lab1p = labels + (size_t)row1 * T_DIM;

    if (row0 < B) {
        const int4   a0 = __ldg((const int4*)(lab0p));
        const int4   a1 = __ldg((const int4*)(lab0p + 4));
        const int4   a2 = __ldg((const int4*)(lab0p + 8));
        const int4   a3 = __ldg((const int4*)(lab0p + 12));
        const float4 b0 = __ldg((const float4*)(p0));
        const float4 b1 = __ldg((const float4*)(p0 + 4));
        const float4 b2 = __ldg((const float4*)(p0 + 8));
        const float4 b3 = __ldg((const float4*)(p0 + 12));
        const float4 b4 = __ldg((const float4*)(p0 + 16));
        const float4 b5 = __ldg((const float4*)(p0 + 20));

        if (row1 < B) {
            const int4   c0 = __ldg((const int4*)(lab1p));
            const int4   c1 = __ldg((const int4*)(lab1p + 4));
            const int4   c2 = __ldg((const int4*)(lab1p + 8));
            const int4   c3 = __ldg((const int4*)(lab1p + 12));
            const float4 d0 = __ldg((const float4*)(p1));
            const float4 d1 = __ldg((const float4*)(p1 + 4));
            const float4 d2 = __ldg((const float4*)(p1 + 8));
            const float4 d3 = __ldg((const float4*)(p1 + 12));
            const float4 d4 = __ldg((const float4*)(p1 + 16));
            const float4 d5 = __ldg((const float4*)(p1 + 20));

            const float pf1[24] = {d0.x,d0.y,d0.z,d0.w, d1.x,d1.y,d1.z,d1.w,
                                   d2.x,d2.y,d2.z,d2.w, d3.x,d3.y,d3.z,d3.w,
                                   d4.x,d4.y,d4.z,d4.w, d5.x,d5.y,d5.z,d5.w};
            const int   la1[16] = {c0.x,c0.y,c0.z,c0.w, c1.x,c1.y,c1.z,c1.w,
                                   c2.x,c2.y,c2.z,c2.w, c3.x,c3.y,c3.z,c3.w};
            acc += row_loss(p1, lab1p, pf1, la1);
        }

        const float pf0[24] = {b0.x,b0.y,b0.z,b0.w, b1.x,b1.y,b1.z,b1.w,
                               b2.x,b2.y,b2.z,b2.w, b3.x,b3.y,b3.z,b3.w,
                               b4.x,b4.y,b4.z,b4.w, b5.x,b5.y,b5.z,b5.w};
        const int   la0[16] = {a0.x,a0.y,a0.z,a0.w, a1.x,a1.y,a1.z,a1.w,
                               a2.x,a2.y,a2.z,a2.w, a3.x,a3.y,a3.z,a3.w};
        acc += row_loss(p0, lab0p, pf0, la0);
    }

    // ---- warp reduce via single HW REDUX.SUM on fixed-point int32 ----
    // scale 2^19: |acc| <= ~73 -> warp sum < 32*73*2^19 ~ 1.2e9 < 2^31.
    const int fixi = __float2int_rn(acc * 524288.0f);
    const int wsum = __reduce_add_sync(FULLMASK, fixi);

    // ---- ONE atomic per warp (128 total): sum + count in one 64-bit word ----
    if (threadIdx.x == 0) {
        long long fix = (long long)wsum + (1LL << 38);          // integer bias
        unsigned long long packed = ((unsigned long long)fix << 16) | 1ULL;
        unsigned long long old = atomicAdd(&g_acc, packed);
        if ((old & 0xFFFFULL) == (unsigned long long)(gridDim.x - 1)) {
            unsigned long long tot = old + packed;              // grand total in hand
            long long net = (long long)(tot >> 16) - ((long long)gridDim.x << 38);
            double sum = (double)net * (1.0 / 524288.0);
            out[0] = (float)(sum / (double)B);
            g_acc = 0ULL;                                       // reset for replay
        }
    }
}

extern "C" void kernel_launch(void* const* d_in, const int* in_sizes, int n_in,
                              void* d_out, int out_size) {
    const float* outputs = (const float*)d_in[0];
    const int*   labels  = (const int*)d_in[1];

    int B = in_sizes[0] / T_DIM;
    if (B > MAX_B) B = MAX_B;

    const int rows_per_blk = BLOCK * ROWS_PER_THREAD;          // 64
    int blocks = (B + rows_per_blk - 1) / rows_per_blk;        // 128 one-warp CTAs
    fused_loss_kernel<<<blocks, BLOCK>>>(outputs, labels, (float*)d_out, B);
}

// round 10
// speedup vs baseline: 1.1982x; 1.1982x over previous
#include <cuda_runtime.h>

#define T_DIM 2048
#define MAX_B 8192
#define BLOCK 32
#define FULLMASK 0xffffffffu

// Single 64-bit accumulator: bits[63:16] = biased fixed-point sum (per-thread
// scale 2^20, bias 2^38 per arriving warp), bits[15:0] = arrived-warp count.
// All additions are integer -> associative -> bitwise-deterministic in any
// arrival order. Last arriver holds the grand total in-hand, stores the mean,
// resets for the next graph replay.
__device__ unsigned long long g_acc = 0ULL;

__global__ __launch_bounds__(BLOCK)
void fused_loss_kernel(const float* __restrict__ outputs,
                       const int* __restrict__ labels,
                       float* __restrict__ out, int B) {
    const int row = blockIdx.x * BLOCK + threadIdx.x;

    float per = 0.0f;
    if (row < B) {
        const float* p   = outputs + (size_t)row * T_DIM;
        const int*   lab = labels  + (size_t)row * T_DIM;

        // ---- Tier A prefetch: 16 labels + 24 outputs, 10 LDG.128 in flight ----
        const int4   l0 = __ldg((const int4*)(lab));
        const int4   l1 = __ldg((const int4*)(lab + 4));
        const int4   l2 = __ldg((const int4*)(lab + 8));
        const int4   l3 = __ldg((const int4*)(lab + 12));
        const float4 q0 = __ldg((const float4*)(p));
        const float4 q1 = __ldg((const float4*)(p + 4));
        const float4 q2 = __ldg((const float4*)(p + 8));
        const float4 q3 = __ldg((const float4*)(p + 12));
        const float4 q4 = __ldg((const float4*)(p + 16));
        const float4 q5 = __ldg((const float4*)(p + 20));

        const float pf[24] = {q0.x,q0.y,q0.z,q0.w, q1.x,q1.y,q1.z,q1.w,
                              q2.x,q2.y,q2.z,q2.w, q3.x,q3.y,q3.z,q3.w,
                              q4.x,q4.y,q4.z,q4.w, q5.x,q5.y,q5.z,q5.w};
        const int   la[16] = {l0.x,l0.y,l0.z,l0.w, l1.x,l1.y,l1.z,l1.w,
                              l2.x,l2.y,l2.z,l2.w, l3.x,l3.y,l3.z,l3.w};

        const int lab0 = la[0];
        int ind0 = T_DIM;
        #pragma unroll
        for (int k = 15; k >= 1; k--)          // descending: smallest k wins
            if (la[k] != lab0) ind0 = k;

        if (ind0 <= 15) {
            // ---- TIER A (P ~ 1 - 2^-15): prefix + full n=8 window, regs only ----
            float S = 0.f, cp = 1.f;
            float term1 = 0.f, cpw = 1.f, cpl = 1.f, pl = 0.f;
            #pragma unroll
            for (int k = 0; k < 24; k++) {
                const float pk = pf[k];
                if (k < ind0) {                         // false-alarm prefix
                    S  += (float)(k + 1) * pk * cp;
                    cp *= 1.f - pk;
                }
                if (k >= ind0 && k < ind0 + 8) {        // delay window
                    const int kk = k - ind0;
                    term1 += (float)(kk + 1) * pk * cpw;
                    if (kk == 7) { cpl = cpw; pl = pk; }
                    cpw *= 1.f - pk;
                }
            }
            const float fa = 1.f - S;
            const float dd = term1 + 72.f * cpl * (1.f - pl);   // n=8, W+1=9
            per = 0.5f * dd + 0.5f * fa;                        // ALPHA=0.5
        } else {
            // ---- TIER B (P ~ 2^-15): ONE more bulk round trip, no serial chase ----
            int4   m0 = __ldg((const int4*)(lab + 16));
            int4   m1 = __ldg((const int4*)(lab + 20));
            int4   m2 = __ldg((const int4*)(lab + 24));
            int4   m3 = __ldg((const int4*)(lab + 28));
            int4   m4 = __ldg((const int4*)(lab + 32));
            int4   m5 = __ldg((const int4*)(lab + 36));
            int4   m6 = __ldg((const int4*)(lab + 40));
            int4   m7 = __ldg((const int4*)(lab + 44));
            float4 r0 = __ldg((const float4*)(p + 24));
            float4 r1 = __ldg((const float4*)(p + 28));
            float4 r2 = __ldg((const float4*)(p + 32));
            float4 r3 = __ldg((const float4*)(p + 36));
            float4 r4 = __ldg((const float4*)(p + 40));
            float4 r5 = __ldg((const float4*)(p + 44));
            float4 r6 = __ldg((const float4*)(p + 48));
            float4 r7 = __ldg((const float4*)(p + 52));

            const int   lb[32] = {m0.x,m0.y,m0.z,m0.w, m1.x,m1.y,m1.z,m1.w,
                                  m2.x,m2.y,m2.z,m2.w, m3.x,m3.y,m3.z,m3.w,
                                  m4.x,m4.y,m4.z,m4.w, m5.x,m5.y,m5.z,m5.w,
                                  m6.x,m6.y,m6.z,m6.w, m7.x,m7.y,m7.z,m7.w};
            const float pg[32] = {r0.x,r0.y,r0.z,r0.w, r1.x,r1.y,r1.z,r1.w,
                                  r2.x,r2.y,r2.z,r2.w, r3.x,r3.y,r3.z,r3.w,
                                  r4.x,r4.y,r4.z,r4.w, r5.x,r5.y,r5.z,r5.w,
                                  r6.x,r6.y,r6.z,r6.w, r7.x,r7.y,r7.z,r7.w};

            #pragma unroll
            for (int k = 31; k >= 0; k--)
                if (lb[k] != lab0) ind0 = 16 + k;

            if (ind0 <= 47) {
                float S = 0.f, cp = 1.f;
                float term1 = 0.f, cpw = 1.f, cpl = 1.f, pl = 0.f;
                #pragma unroll
                for (int k = 0; k < 56; k++) {
                    const float pk = (k < 24) ? pf[k] : pg[k - 24];
                    if (k < ind0) {
                        S  += (float)(k + 1) * pk * cp;
                        cp *= 1.f - pk;
                    }
                    if (k >= ind0 && k < ind0 + 8) {
                        const int kk = k - ind0;
                        term1 += (float)(kk + 1) * pk * cpw;
                        if (kk == 7) { cpl = cpw; pl = pk; }
                        cpw *= 1.f - pk;
                    }
                }
                const float fa = 1.f - S;
                const float dd = term1 + 72.f * cpl * (1.f - pl);
                per = 0.5f * dd + 0.5f * fa;
            } else {
                // ---- TIER C (P ~ 2^-47): fully general, correctness only ----
                ind0 = T_DIM;
                for (int base = 48; base < T_DIM; base += 4) {
                    int4 v = __ldg((const int4*)(lab + base));
                    if (v.x != lab0) { ind0 = base;     break; }
                    if (v.y != lab0) { ind0 = base + 1; break; }
                    if (v.z != lab0) { ind0 = base + 2; break; }
                    if (v.w != lab0) { ind0 = base + 3; break; }
                }
                const bool has_change = (ind0 < T_DIM);
                const int  L = has_change ? ind0 : T_DIM;
                float S = 0.f, cp = 1.f;
                for (int k = 0; k < L; k++) {
                    const float pk = p[k];
                    S  += (float)(k + 1) * pk * cp;
                    cp *= 1.f - pk;
                }
                const float fa = 1.f - S;
                if (has_change) {
                    int n = T_DIM - ind0; if (n > 8) n = 8;
                    float cpw = 1.f, term1 = 0.f, cpl = 1.f, pl = 0.f;
                    for (int kk = 0; kk < n; kk++) {
                        const float pk = p[ind0 + kk];
                        term1 += (float)(kk + 1) * pk * cpw;
                        if (kk == n - 1) { cpl = cpw; pl = pk; }
                        cpw *= 1.f - pk;
                    }
                    const float dd = term1 + (float)n * 9.f * cpl * (1.f - pl);
                    per = 0.5f * dd + 0.5f * fa;
                } else {
                    per = fa;
                }
            }
        }
    }

    // ---- warp reduce via single HW REDUX.SUM on fixed-point int32 ----
    // per-thread scale 2^20: |per| <= ~36.5 -> warp sum < 2^31, no overflow.
    const int   fixi = __float2int_rn(per * 1048576.0f);
    const int   wsum = __reduce_add_sync(FULLMASK, fixi);

    // ---- ONE atomic per warp: sum + count packed in one 64-bit word ----
    if (threadIdx.x == 0) {
        long long fix = (long long)wsum + (1LL << 38);          // integer bias
        unsigned long long packed = ((unsigned long long)fix << 16) | 1ULL;
        unsigned long long old = atomicAdd(&g_acc, packed);
        if ((old & 0xFFFFULL) == (unsigned long long)(gridDim.x - 1)) {
            unsigned long long tot = old + packed;              // grand total in hand
            long long net = (long long)(tot >> 16) - ((long long)gridDim.x << 38);
            double sum = (double)net * (1.0 / 1048576.0);
            __stcg(out, (float)(sum / (double)B));              // L2 write-through
            g_acc = 0ULL;                                       // reset for replay
        }
    }
}

extern "C" void kernel_launch(void* const* d_in, const int* in_sizes, int n_in,
                              void* d_out, int out_size) {
    const float* outputs = (const float*)d_in[0];
    const int*   labels  = (const int*)d_in[1];

    int B = in_sizes[0] / T_DIM;
    if (B > MAX_B) B = MAX_B;

    int blocks = (B + BLOCK - 1) / BLOCK;     // 256 one-warp CTAs (best measured)
    fused_loss_kernel<<<blocks, BLOCK>>>(outputs, labels, (float*)d_out, B);
}

// round 11
// speedup vs baseline: 1.3140x; 1.0966x over previous
#include <cuda_runtime.h>

#define T_DIM 2048
#define MAX_B 8192
#define BLOCK 32
#define FULLMASK 0xffffffffu

// Single 64-bit accumulator: bits[63:16] = biased fixed-point sum (per-thread
// scale 2^20, bias 2^38 per arriving warp), bits[15:0] = arrived-warp count.
// All additions are integer -> associative -> bitwise-deterministic in any
// arrival order. Last arriver holds the grand total in-hand, stores the mean,
// resets for the next graph replay.
__device__ unsigned long long g_acc = 0ULL;

__global__ __launch_bounds__(BLOCK)
void fused_loss_kernel(const float* __restrict__ outputs,
                       const int* __restrict__ labels,
                       float* __restrict__ out, int B) {
    const int row = blockIdx.x * BLOCK + threadIdx.x;

    float per = 0.0f;
    if (row < B) {
        const float* p   = outputs + (size_t)row * T_DIM;
        const int*   lab = labels  + (size_t)row * T_DIM;

        // ---- Tier A prefetch: 16 labels + 24 outputs, 10 LDG.128 in flight ----
        const int4   l0 = __ldg((const int4*)(lab));
        const int4   l1 = __ldg((const int4*)(lab + 4));
        const int4   l2 = __ldg((const int4*)(lab + 8));
        const int4   l3 = __ldg((const int4*)(lab + 12));
        const float4 q0 = __ldg((const float4*)(p));
        const float4 q1 = __ldg((const float4*)(p + 4));
        const float4 q2 = __ldg((const float4*)(p + 8));
        const float4 q3 = __ldg((const float4*)(p + 12));
        const float4 q4 = __ldg((const float4*)(p + 16));
        const float4 q5 = __ldg((const float4*)(p + 20));

        const float pf[24] = {q0.x,q0.y,q0.z,q0.w, q1.x,q1.y,q1.z,q1.w,
                              q2.x,q2.y,q2.z,q2.w, q3.x,q3.y,q3.z,q3.w,
                              q4.x,q4.y,q4.z,q4.w, q5.x,q5.y,q5.z,q5.w};
        const int   la[16] = {l0.x,l0.y,l0.z,l0.w, l1.x,l1.y,l1.z,l1.w,
                              l2.x,l2.y,l2.z,l2.w, l3.x,l3.y,l3.z,l3.w};

        const int lab0 = la[0];
        int ind0 = T_DIM;
        #pragma unroll
        for (int k = 15; k >= 1; k--)          // descending: smallest k wins
            if (la[k] != lab0) ind0 = k;

        if (ind0 <= 15) {
            // ---- TIER A (P ~ 1 - 2^-15): prefix + full n=8 window, regs only ----
            float S = 0.f, cp = 1.f;
            float term1 = 0.f, cpw = 1.f, cpl = 1.f, pl = 0.f;
            #pragma unroll
            for (int k = 0; k < 24; k++) {
                const float pk = pf[k];
                if (k < ind0) {                         // false-alarm prefix
                    S  += (float)(k + 1) * pk * cp;
                    cp *= 1.f - pk;
                }
                if (k >= ind0 && k < ind0 + 8) {        // delay window
                    const int kk = k - ind0;
                    term1 += (float)(kk + 1) * pk * cpw;
                    if (kk == 7) { cpl = cpw; pl = pk; }
                    cpw *= 1.f - pk;
                }
            }
            const float fa = 1.f - S;
            const float dd = term1 + 72.f * cpl * (1.f - pl);   // n=8, W+1=9
            per = 0.5f * dd + 0.5f * fa;                        // ALPHA=0.5
        } else {
            // ---- TIER B (P ~ 2^-15): ONE more bulk round trip, no serial chase ----
            int4   m0 = __ldg((const int4*)(lab + 16));
            int4   m1 = __ldg((const int4*)(lab + 20));
            int4   m2 = __ldg((const int4*)(lab + 24));
            int4   m3 = __ldg((const int4*)(lab + 28));
            int4   m4 = __ldg((const int4*)(lab + 32));
            int4   m5 = __ldg((const int4*)(lab + 36));
            int4   m6 = __ldg((const int4*)(lab + 40));
            int4   m7 = __ldg((const int4*)(lab + 44));
            float4 r0 = __ldg((const float4*)(p + 24));
            float4 r1 = __ldg((const float4*)(p + 28));
            float4 r2 = __ldg((const float4*)(p + 32));
            float4 r3 = __ldg((const float4*)(p + 36));
            float4 r4 = __ldg((const float4*)(p + 40));
            float4 r5 = __ldg((const float4*)(p + 44));
            float4 r6 = __ldg((const float4*)(p + 48));
            float4 r7 = __ldg((const float4*)(p + 52));

            const int   lb[32] = {m0.x,m0.y,m0.z,m0.w, m1.x,m1.y,m1.z,m1.w,
                                  m2.x,m2.y,m2.z,m2.w, m3.x,m3.y,m3.z,m3.w,
                                  m4.x,m4.y,m4.z,m4.w, m5.x,m5.y,m5.z,m5.w,
                                  m6.x,m6.y,m6.z,m6.w, m7.x,m7.y,m7.z,m7.w};
            const float pg[32] = {r0.x,r0.y,r0.z,r0.w, r1.x,r1.y,r1.z,r1.w,
                                  r2.x,r2.y,r2.z,r2.w, r3.x,r3.y,r3.z,r3.w,
                                  r4.x,r4.y,r4.z,r4.w, r5.x,r5.y,r5.z,r5.w,
                                  r6.x,r6.y,r6.z,r6.w, r7.x,r7.y,r7.z,r7.w};

            #pragma unroll
            for (int k = 31; k >= 0; k--)
                if (lb[k] != lab0) ind0 = 16 + k;

            if (ind0 <= 47) {
                float S = 0.f, cp = 1.f;
                float term1 = 0.f, cpw = 1.f, cpl = 1.f, pl = 0.f;
                #pragma unroll
                for (int k = 0; k < 56; k++) {
                    const float pk = (k < 24) ? pf[k] : pg[k - 24];
                    if (k < ind0) {
                        S  += (float)(k + 1) * pk * cp;
                        cp *= 1.f - pk;
                    }
                    if (k >= ind0 && k < ind0 + 8) {
                        const int kk = k - ind0;
                        term1 += (float)(kk + 1) * pk * cpw;
                        if (kk == 7) { cpl = cpw; pl = pk; }
                        cpw *= 1.f - pk;
                    }
                }
                const float fa = 1.f - S;
                const float dd = term1 + 72.f * cpl * (1.f - pl);
                per = 0.5f * dd + 0.5f * fa;
            } else {
                // ---- TIER C (P ~ 2^-47): fully general, correctness only ----
                ind0 = T_DIM;
                for (int base = 48; base < T_DIM; base += 4) {
                    int4 v = __ldg((const int4*)(lab + base));
                    if (v.x != lab0) { ind0 = base;     break; }
                    if (v.y != lab0) { ind0 = base + 1; break; }
                    if (v.z != lab0) { ind0 = base + 2; break; }
                    if (v.w != lab0) { ind0 = base + 3; break; }
                }
                const bool has_change = (ind0 < T_DIM);
                const int  L = has_change ? ind0 : T_DIM;
                float S = 0.f, cp = 1.f;
                for (int k = 0; k < L; k++) {
                    const float pk = p[k];
                    S  += (float)(k + 1) * pk * cp;
                    cp *= 1.f - pk;
                }
                const float fa = 1.f - S;
                if (has_change) {
                    int n = T_DIM - ind0; if (n > 8) n = 8;
                    float cpw = 1.f, term1 = 0.f, cpl = 1.f, pl = 0.f;
                    for (int kk = 0; kk < n; kk++) {
                        const float pk = p[ind0 + kk];
                        term1 += (float)(kk + 1) * pk * cpw;
                        if (kk == n - 1) { cpl = cpw; pl = pk; }
                        cpw *= 1.f - pk;
                    }
                    const float dd = term1 + (float)n * 9.f * cpl * (1.f - pl);
                    per = 0.5f * dd + 0.5f * fa;
                } else {
                    per = fa;
                }
            }
        }
    }

    // ---- warp reduce via single HW REDUX.SUM on fixed-point int32 ----
    // per-thread scale 2^20: |per| <= ~36.5 -> warp sum < 2^31, no overflow.
    const int   fixi = __float2int_rn(per * 1048576.0f);
    const int   wsum = __reduce_add_sync(FULLMASK, fixi);

    // ---- ONE atomic per warp: sum + count packed in one 64-bit word ----
    if (threadIdx.x == 0) {
        long long fix = (long long)wsum + (1LL << 38);          // integer bias
        unsigned long long packed = ((unsigned long long)fix << 16) | 1ULL;
        unsigned long long old = atomicAdd(&g_acc, packed);
        if ((old & 0xFFFFULL) == (unsigned long long)(gridDim.x - 1)) {
            unsigned long long tot = old + packed;              // grand total in hand
            long long net = (long long)(tot >> 16) - ((long long)gridDim.x << 38);
            double sum = (double)net * (1.0 / 1048576.0);
            out[0] = (float)(sum / (double)B);
            g_acc = 0ULL;                                       // reset for replay
        }
    }
}

extern "C" void kernel_launch(void* const* d_in, const int* in_sizes, int n_in,
                              void* d_out, int out_size) {
    const float* outputs = (const float*)d_in[0];
    const int*   labels  = (const int*)d_in[1];

    int B = in_sizes[0] / T_DIM;
    if (B > MAX_B) B = MAX_B;

    int blocks = (B + BLOCK - 1) / BLOCK;     // 256 one-warp CTAs (best measured)
    fused_loss_kernel<<<blocks, BLOCK>>>(outputs, labels, (float*)d_out, B);
}